// round 1
// baseline (speedup 1.0000x reference)
#include <cuda_runtime.h>

// Problem constants (fixed by the reference): fm is (1, 256, 256, 256) fp32 NHWC,
// rois (2000, 5) int32 [batch, x, y, w, h], pool = 7.
#define FM_W 256
#define FM_C 256
#define POOLSZ 7

__global__ __launch_bounds__(256) void roi_pool_kernel(
    const float* __restrict__ fm,      // [H, W, C]
    const int* __restrict__ rois,      // [N, 5]
    float* __restrict__ out,           // [N, 7, 7, C]
    int n_pix)                         // N * 49
{
    int pid = blockIdx.x * 4 + threadIdx.y;
    if (pid >= n_pix) return;

    int roi = pid / 49;
    int rem = pid - roi * 49;
    int py = rem / 7;
    int px = rem - py * 7;

    int rx = rois[roi * 5 + 1];
    int ry = rois[roi * 5 + 2];
    int rw = rois[roi * 5 + 3];
    int rh = rois[roi * 5 + 4];

    // y axis: f = (py + 0.5) * (h / 7) - 0.5, clamp [0, h-1]
    float lh = (float)rh;
    float fyc = ((float)py + 0.5f) * (lh / (float)POOLSZ) - 0.5f;
    fyc = fminf(fmaxf(fyc, 0.0f), lh - 1.0f);
    int iy0 = (int)floorf(fyc);
    int iy1 = min(iy0 + 1, rh - 1);
    float fy = fyc - (float)iy0;

    // x axis
    float lw = (float)rw;
    float fxc = ((float)px + 0.5f) * (lw / (float)POOLSZ) - 0.5f;
    fxc = fminf(fmaxf(fxc, 0.0f), lw - 1.0f);
    int ix0 = (int)floorf(fxc);
    int ix1 = min(ix0 + 1, rw - 1);
    float fx = fxc - (float)ix0;

    int y0 = ry + iy0, y1 = ry + iy1;
    int x0 = rx + ix0, x1 = rx + ix1;

    // float4 view: each (y,x) pixel is 256 floats = 64 float4; thread c in [0,64)
    const float4* f4 = (const float4*)fm;
    int c = threadIdx.x;

    const float4 g00 = f4[(y0 * FM_W + x0) * (FM_C / 4) + c];
    const float4 g01 = f4[(y0 * FM_W + x1) * (FM_C / 4) + c];
    const float4 g10 = f4[(y1 * FM_W + x0) * (FM_C / 4) + c];
    const float4 g11 = f4[(y1 * FM_W + x1) * (FM_C / 4) + c];

    float ofx = 1.0f - fx;
    float ofy = 1.0f - fy;

    float4 r;
    {
        float top = g00.x * ofx + g01.x * fx;
        float bot = g10.x * ofx + g11.x * fx;
        r.x = top * ofy + bot * fy;
    }
    {
        float top = g00.y * ofx + g01.y * fx;
        float bot = g10.y * ofx + g11.y * fx;
        r.y = top * ofy + bot * fy;
    }
    {
        float top = g00.z * ofx + g01.z * fx;
        float bot = g10.z * ofx + g11.z * fx;
        r.z = top * ofy + bot * fy;
    }
    {
        float top = g00.w * ofx + g01.w * fx;
        float bot = g10.w * ofx + g11.w * fx;
        r.w = top * ofy + bot * fy;
    }

    ((float4*)out)[pid * (FM_C / 4) + c] = r;
}

extern "C" void kernel_launch(void* const* d_in, const int* in_sizes, int n_in,
                              void* d_out, int out_size)
{
    const float* fm  = (const float*)d_in[0];
    const int* rois  = (const int*)d_in[1];
    float* out       = (float*)d_out;

    int n_rois = in_sizes[1] / 5;
    int n_pix  = n_rois * POOLSZ * POOLSZ;

    dim3 block(64, 4, 1);
    dim3 grid((n_pix + 3) / 4, 1, 1);
    roi_pool_kernel<<<grid, block>>>(fm, rois, out, n_pix);
}